// round 1
// baseline (speedup 1.0000x reference)
#include <cuda_runtime.h>
#include <cstdint>

#define BH    64          // B*h
#define DIM   32          // d
#define LPIX  4096        // H*W
#define MM    64          // number of clusters (L_)
#define QK_SCALE 0.17677669529663687f

// ---- device scratch (no allocations allowed) ----
__device__ __align__(256) float g_cq0[BH * MM * DIM];      // 512 KB
__device__ __align__(256) float g_rpb0[LPIX * MM];         // 1 MB  (input-independent)
__device__ __align__(256) unsigned char g_assign[BH * LPIX]; // 256 KB
__device__ __align__(256) float g_centers[BH * MM * 2];    // 32 KB

__device__ __forceinline__ float sqrt_ap(float x) {
    float y; asm("sqrt.approx.f32 %0, %1;" : "=f"(y) : "f"(x)); return y;
}

// ---------------------------------------------------------------------------
// K0: rpb0[l][m] = exp(-dist(pixel l, fixed window center m))  (no input dep)
// ---------------------------------------------------------------------------
__global__ void k_rpb0() {
    int idx = blockIdx.x * 256 + threadIdx.x;   // over LPIX*MM/4 float4s
    int m0 = (idx & 15) * 4;
    int l  = idx >> 4;
    float fi = (float)(l >> 6), fj = (float)(l & 63);
    float4 r;
    float* rp = &r.x;
#pragma unroll
    for (int q = 0; q < 4; q++) {
        int m = m0 + q;
        float ch = (float)((m >> 3) << 3) + 3.5f;
        float cw = (float)((m & 7) << 3) + 3.5f;
        float dh = fi - ch, dw = fj - cw;
        rp[q] = __expf(-sqrt_ap(dh * dh + dw * dw));
    }
    ((float4*)g_rpb0)[idx] = r;
}

// ---------------------------------------------------------------------------
// K1: c_q0[bh][m][:] = l2norm(mean over 8x8 window of x_k)
// one block per (bh, m); 8 warps, warp w handles window row w
// ---------------------------------------------------------------------------
__global__ void k_cq0(const float* __restrict__ xk) {
    int blk = blockIdx.x;
    int bh = blk >> 6, m = blk & 63;
    int wr = m >> 3, wc = m & 7;
    int warp = threadIdx.x >> 5, lane = threadIdx.x & 31;

    const float* row = xk + (size_t)bh * LPIX * DIM
                          + ((size_t)(wr * 8 + warp) * 64 + wc * 8) * DIM;
    float acc = 0.f;
#pragma unroll
    for (int k = 0; k < 8; k++) acc += row[k * 32 + lane];

    __shared__ float s[8][32];
    s[warp][lane] = acc;
    __syncthreads();
    if (warp == 0) {
        float v = 0.f;
#pragma unroll
        for (int w = 0; w < 8; w++) v += s[w][lane];
        v *= (1.0f / 64.0f);
        float sq = v * v;
#pragma unroll
        for (int o = 16; o > 0; o >>= 1) sq += __shfl_xor_sync(0xffffffffu, sq, o);
        float inv = 1.0f / fmaxf(sqrt_ap(sq), 1e-12f);
        g_cq0[((size_t)bh * 64 + m) * 32 + lane] = v * inv;
    }
}

// ---------------------------------------------------------------------------
// K2a: per-pixel argmax over 64 clusters of qs*<x_k, c_q0> + rpb0
// grid (8 pixel-chunks, 64 bh), 512 threads, 1 pixel/thread
// ---------------------------------------------------------------------------
__global__ void __launch_bounds__(512) k_assign(const float* __restrict__ xk,
                                                const float* __restrict__ scale) {
    int bh = blockIdx.y;
    int l  = blockIdx.x * 512 + threadIdx.x;

    __shared__ float4 scq[MM * 8];  // 64 clusters x 32 floats
    const float4* gq = (const float4*)(g_cq0 + (size_t)bh * MM * DIM);
    scq[threadIdx.x] = gq[threadIdx.x];
    __syncthreads();

    float qs = QK_SCALE * scale[0];
    float xq[32];
    const float4* xr = (const float4*)(xk + (size_t)bh * LPIX * DIM + (size_t)l * DIM);
#pragma unroll
    for (int k = 0; k < 8; k++) {
        float4 v = xr[k];
        xq[4 * k + 0] = v.x * qs; xq[4 * k + 1] = v.y * qs;
        xq[4 * k + 2] = v.z * qs; xq[4 * k + 3] = v.w * qs;
    }

    const float4* rp = (const float4*)(g_rpb0 + (size_t)l * MM);
    float maxv = -1e30f;
    int argm = 0;
    for (int mq = 0; mq < 16; mq++) {
        float4 rb = rp[mq];
        float a0 = rb.x, a1 = rb.y, a2 = rb.z, a3 = rb.w;
#pragma unroll
        for (int k = 0; k < 8; k++) {
            float4 c0 = scq[(4 * mq + 0) * 8 + k];
            float4 c1 = scq[(4 * mq + 1) * 8 + k];
            float4 c2 = scq[(4 * mq + 2) * 8 + k];
            float4 c3 = scq[(4 * mq + 3) * 8 + k];
            float x0 = xq[4 * k + 0], x1 = xq[4 * k + 1],
                  x2 = xq[4 * k + 2], x3 = xq[4 * k + 3];
            a0 += x0 * c0.x + x1 * c0.y + x2 * c0.z + x3 * c0.w;
            a1 += x0 * c1.x + x1 * c1.y + x2 * c1.z + x3 * c1.w;
            a2 += x0 * c2.x + x1 * c2.y + x2 * c2.z + x3 * c2.w;
            a3 += x0 * c3.x + x1 * c3.y + x2 * c3.z + x3 * c3.w;
        }
        // keep first-argmax semantics (ascending m)
        if (a0 > maxv) { maxv = a0; argm = 4 * mq + 0; }
        if (a1 > maxv) { maxv = a1; argm = 4 * mq + 1; }
        if (a2 > maxv) { maxv = a2; argm = 4 * mq + 2; }
        if (a3 > maxv) { maxv = a3; argm = 4 * mq + 3; }
    }
    g_assign[(size_t)bh * LPIX + l] = (unsigned char)argm;
}

// ---------------------------------------------------------------------------
// K2b: per (bh, m) gather: sums of x_k -> c_q (l2norm), x_v -> c_v (/count),
// coordinate means -> g_centers. Ballot-based, no atomics.
// grid 4096 blocks, 128 threads (4 warps); lane == dim
// ---------------------------------------------------------------------------
__global__ void __launch_bounds__(128) k_gather(const float* __restrict__ xk,
                                                const float* __restrict__ xv,
                                                float* __restrict__ out) {
    int blk = blockIdx.x;
    int bh = blk >> 6, m = blk & 63;
    int warp = threadIdx.x >> 5, lane = threadIdx.x & 31;

    __shared__ unsigned char sa[LPIX];
    const uint4* ga = (const uint4*)(g_assign + (size_t)bh * LPIX);  // 256 uint4
    uint4* sa4 = (uint4*)sa;
    for (int t = threadIdx.x; t < 256; t += 128) sa4[t] = ga[t];
    __syncthreads();

    const float* xkb = xk + (size_t)bh * LPIX * DIM;
    const float* xvb = xv + (size_t)bh * LPIX * DIM;

    float accK = 0.f, accV = 0.f, cnt = 0.f, si = 0.f, sj = 0.f;
    unsigned char mm = (unsigned char)m;
    for (int it = 0; it < 32; ++it) {
        int base = warp * 1024 + it * 32;
        unsigned int match = __ballot_sync(0xffffffffu, sa[base + lane] == mm);
        while (match) {
            int b = __ffs(match) - 1;
            match &= match - 1;
            int l2 = base + b;
            accK += xkb[(size_t)l2 * 32 + lane];
            accV += xvb[(size_t)l2 * 32 + lane];
            cnt += 1.0f;
            si += (float)(l2 >> 6);
            sj += (float)(l2 & 63);
        }
    }

    __shared__ float sk[4][32], sv[4][32], sc[4], ssi[4], ssj[4];
    sk[warp][lane] = accK;
    sv[warp][lane] = accV;
    if (lane == 0) { sc[warp] = cnt; ssi[warp] = si; ssj[warp] = sj; }
    __syncthreads();

    if (warp == 0) {
        float k4 = sk[0][lane] + sk[1][lane] + sk[2][lane] + sk[3][lane];
        float v4 = sv[0][lane] + sv[1][lane] + sv[2][lane] + sv[3][lane];
        float c   = sc[0] + sc[1] + sc[2] + sc[3];
        float tsi = ssi[0] + ssi[1] + ssi[2] + ssi[3];
        float tsj = ssj[0] + ssj[1] + ssj[2] + ssj[3];
        float denom = (c > 0.f) ? c : 1.0f;   // matches s==0 -> 1 guard

        if (lane == 0) {
            g_centers[((size_t)bh * 64 + m) * 2 + 0] = tsi / denom;
            g_centers[((size_t)bh * 64 + m) * 2 + 1] = tsj / denom;
        }
        // c_v
        out[131072 + ((size_t)bh * 64 + m) * 32 + lane] = v4 / denom;
        // c_q = l2norm(sum)
        float sq = k4 * k4;
#pragma unroll
        for (int o = 16; o > 0; o >>= 1) sq += __shfl_xor_sync(0xffffffffu, sq, o);
        float inv = 1.0f / fmaxf(sqrt_ap(sq), 1e-12f);
        out[((size_t)bh * 64 + m) * 32 + lane] = k4 * inv;
    }
}

// ---------------------------------------------------------------------------
// K3: rpb[bh][l][m] = exp(-dist(pixel l, center[bh][m]))
// grid (256 pixel-groups, 64 bh); block 256 = 16 pixels x 16 m-quads
// ---------------------------------------------------------------------------
__global__ void __launch_bounds__(256) k_rpb(float* __restrict__ out) {
    int bh = blockIdx.y;
    __shared__ float2 sc[MM];
    if (threadIdx.x < 64)
        sc[threadIdx.x] = ((const float2*)(g_centers + (size_t)bh * 128))[threadIdx.x];
    __syncthreads();

    int pix = threadIdx.x >> 4;     // 0..15
    int mg  = threadIdx.x & 15;     // 0..15 (quad of m)
    int l = blockIdx.x * 16 + pix;
    float fi = (float)(l >> 6), fj = (float)(l & 63);
    float4 r;
#pragma unroll
    for (int q = 0; q < 4; q++) {
        float2 c = sc[mg * 4 + q];
        float dh = fi - c.x, dw = fj - c.y;
        (&r.x)[q] = __expf(-sqrt_ap(dh * dh + dw * dw));
    }
    ((float4*)(out + 262144))[(size_t)bh * 65536 + (size_t)l * 16 + mg] = r;
}

// ---------------------------------------------------------------------------
extern "C" void kernel_launch(void* const* d_in, const int* in_sizes, int n_in,
                              void* d_out, int out_size) {
    const float* xk    = (const float*)d_in[0];
    const float* xv    = (const float*)d_in[1];
    const float* scale = (const float*)d_in[2];
    float* out = (float*)d_out;

    k_rpb0<<<256, 256>>>();
    k_cq0<<<4096, 256>>>(xk);
    dim3 g2(8, 64);
    k_assign<<<g2, 512>>>(xk, scale);
    k_gather<<<4096, 128>>>(xk, xv, out);
    dim3 g3(256, 64);
    k_rpb<<<g3, 256>>>(out);
}

// round 2
// speedup vs baseline: 1.0026x; 1.0026x over previous
#include <cuda_runtime.h>
#include <cstdint>

#define BH    64          // B*h
#define DIM   32          // d
#define LPIX  4096        // H*W
#define MM    64          // number of clusters (L_)
#define QK_SCALE 0.17677669529663687f

// ---- device scratch (no allocations allowed) ----
__device__ __align__(256) float g_cq0[BH * MM * DIM];      // 512 KB
__device__ __align__(256) float g_rpb0[LPIX * MM];         // 1 MB  (input-independent)
__device__ __align__(256) unsigned char g_assign[BH * LPIX]; // 256 KB
__device__ __align__(256) float g_centers[BH * MM * 2];    // 32 KB

__device__ __forceinline__ float sqrt_ap(float x) {
    float y; asm("sqrt.approx.f32 %0, %1;" : "=f"(y) : "f"(x)); return y;
}

// ---------------------------------------------------------------------------
// K0: rpb0[l][m] = exp(-dist(pixel l, fixed window center m))  (no input dep)
// ---------------------------------------------------------------------------
__global__ void k_rpb0() {
    int idx = blockIdx.x * 256 + threadIdx.x;   // over LPIX*MM/4 float4s
    int m0 = (idx & 15) * 4;
    int l  = idx >> 4;
    float fi = (float)(l >> 6), fj = (float)(l & 63);
    float4 r;
    float* rp = &r.x;
#pragma unroll
    for (int q = 0; q < 4; q++) {
        int m = m0 + q;
        float ch = (float)((m >> 3) << 3) + 3.5f;
        float cw = (float)((m & 7) << 3) + 3.5f;
        float dh = fi - ch, dw = fj - cw;
        rp[q] = __expf(-sqrt_ap(dh * dh + dw * dw));
    }
    ((float4*)g_rpb0)[idx] = r;
}

// ---------------------------------------------------------------------------
// K1: c_q0[bh][m][:] = l2norm(mean over 8x8 window of x_k)
// one block per (bh, m); 8 warps, warp w handles window row w
// ---------------------------------------------------------------------------
__global__ void k_cq0(const float* __restrict__ xk) {
    int blk = blockIdx.x;
    int bh = blk >> 6, m = blk & 63;
    int wr = m >> 3, wc = m & 7;
    int warp = threadIdx.x >> 5, lane = threadIdx.x & 31;

    const float* row = xk + (size_t)bh * LPIX * DIM
                          + ((size_t)(wr * 8 + warp) * 64 + wc * 8) * DIM;
    float acc = 0.f;
#pragma unroll
    for (int k = 0; k < 8; k++) acc += row[k * 32 + lane];

    __shared__ float s[8][32];
    s[warp][lane] = acc;
    __syncthreads();
    if (warp == 0) {
        float v = 0.f;
#pragma unroll
        for (int w = 0; w < 8; w++) v += s[w][lane];
        v *= (1.0f / 64.0f);
        float sq = v * v;
#pragma unroll
        for (int o = 16; o > 0; o >>= 1) sq += __shfl_xor_sync(0xffffffffu, sq, o);
        float inv = 1.0f / fmaxf(sqrt_ap(sq), 1e-12f);
        g_cq0[((size_t)bh * 64 + m) * 32 + lane] = v * inv;
    }
}

// ---------------------------------------------------------------------------
// K2a: per-pixel argmax over 64 clusters of qs*<x_k, c_q0> + rpb0
// grid (8 pixel-chunks, 64 bh), 512 threads, 1 pixel/thread
// ---------------------------------------------------------------------------
__global__ void __launch_bounds__(512) k_assign(const float* __restrict__ xk,
                                                const float* __restrict__ scale) {
    int bh = blockIdx.y;
    int l  = blockIdx.x * 512 + threadIdx.x;

    __shared__ float4 scq[MM * 8];  // 64 clusters x 32 floats
    const float4* gq = (const float4*)(g_cq0 + (size_t)bh * MM * DIM);
    scq[threadIdx.x] = gq[threadIdx.x];
    __syncthreads();

    float qs = QK_SCALE * scale[0];
    float xq[32];
    const float4* xr = (const float4*)(xk + (size_t)bh * LPIX * DIM + (size_t)l * DIM);
#pragma unroll
    for (int k = 0; k < 8; k++) {
        float4 v = xr[k];
        xq[4 * k + 0] = v.x * qs; xq[4 * k + 1] = v.y * qs;
        xq[4 * k + 2] = v.z * qs; xq[4 * k + 3] = v.w * qs;
    }

    const float4* rp = (const float4*)(g_rpb0 + (size_t)l * MM);
    float maxv = -1e30f;
    int argm = 0;
    for (int mq = 0; mq < 16; mq++) {
        float4 rb = rp[mq];
        float a0 = rb.x, a1 = rb.y, a2 = rb.z, a3 = rb.w;
#pragma unroll
        for (int k = 0; k < 8; k++) {
            float4 c0 = scq[(4 * mq + 0) * 8 + k];
            float4 c1 = scq[(4 * mq + 1) * 8 + k];
            float4 c2 = scq[(4 * mq + 2) * 8 + k];
            float4 c3 = scq[(4 * mq + 3) * 8 + k];
            float x0 = xq[4 * k + 0], x1 = xq[4 * k + 1],
                  x2 = xq[4 * k + 2], x3 = xq[4 * k + 3];
            a0 += x0 * c0.x + x1 * c0.y + x2 * c0.z + x3 * c0.w;
            a1 += x0 * c1.x + x1 * c1.y + x2 * c1.z + x3 * c1.w;
            a2 += x0 * c2.x + x1 * c2.y + x2 * c2.z + x3 * c2.w;
            a3 += x0 * c3.x + x1 * c3.y + x2 * c3.z + x3 * c3.w;
        }
        // keep first-argmax semantics (ascending m)
        if (a0 > maxv) { maxv = a0; argm = 4 * mq + 0; }
        if (a1 > maxv) { maxv = a1; argm = 4 * mq + 1; }
        if (a2 > maxv) { maxv = a2; argm = 4 * mq + 2; }
        if (a3 > maxv) { maxv = a3; argm = 4 * mq + 3; }
    }
    g_assign[(size_t)bh * LPIX + l] = (unsigned char)argm;
}

// ---------------------------------------------------------------------------
// K2b: per (bh, m) gather: sums of x_k -> c_q (l2norm), x_v -> c_v (/count),
// coordinate means -> g_centers. Ballot-based, no atomics.
// grid 4096 blocks, 128 threads (4 warps); lane == dim
// ---------------------------------------------------------------------------
__global__ void __launch_bounds__(128) k_gather(const float* __restrict__ xk,
                                                const float* __restrict__ xv,
                                                float* __restrict__ out) {
    int blk = blockIdx.x;
    int bh = blk >> 6, m = blk & 63;
    int warp = threadIdx.x >> 5, lane = threadIdx.x & 31;

    __shared__ unsigned char sa[LPIX];
    const uint4* ga = (const uint4*)(g_assign + (size_t)bh * LPIX);  // 256 uint4
    uint4* sa4 = (uint4*)sa;
    for (int t = threadIdx.x; t < 256; t += 128) sa4[t] = ga[t];
    __syncthreads();

    const float* xkb = xk + (size_t)bh * LPIX * DIM;
    const float* xvb = xv + (size_t)bh * LPIX * DIM;

    float accK = 0.f, accV = 0.f, cnt = 0.f, si = 0.f, sj = 0.f;
    unsigned char mm = (unsigned char)m;
    for (int it = 0; it < 32; ++it) {
        int base = warp * 1024 + it * 32;
        unsigned int match = __ballot_sync(0xffffffffu, sa[base + lane] == mm);
        while (match) {
            int b = __ffs(match) - 1;
            match &= match - 1;
            int l2 = base + b;
            accK += xkb[(size_t)l2 * 32 + lane];
            accV += xvb[(size_t)l2 * 32 + lane];
            cnt += 1.0f;
            si += (float)(l2 >> 6);
            sj += (float)(l2 & 63);
        }
    }

    __shared__ float sk[4][32], sv[4][32], sc[4], ssi[4], ssj[4];
    sk[warp][lane] = accK;
    sv[warp][lane] = accV;
    if (lane == 0) { sc[warp] = cnt; ssi[warp] = si; ssj[warp] = sj; }
    __syncthreads();

    if (warp == 0) {
        float k4 = sk[0][lane] + sk[1][lane] + sk[2][lane] + sk[3][lane];
        float v4 = sv[0][lane] + sv[1][lane] + sv[2][lane] + sv[3][lane];
        float c   = sc[0] + sc[1] + sc[2] + sc[3];
        float tsi = ssi[0] + ssi[1] + ssi[2] + ssi[3];
        float tsj = ssj[0] + ssj[1] + ssj[2] + ssj[3];
        float denom = (c > 0.f) ? c : 1.0f;   // matches s==0 -> 1 guard

        if (lane == 0) {
            g_centers[((size_t)bh * 64 + m) * 2 + 0] = tsi / denom;
            g_centers[((size_t)bh * 64 + m) * 2 + 1] = tsj / denom;
        }
        // c_v
        out[131072 + ((size_t)bh * 64 + m) * 32 + lane] = v4 / denom;
        // c_q = l2norm(sum)
        float sq = k4 * k4;
#pragma unroll
        for (int o = 16; o > 0; o >>= 1) sq += __shfl_xor_sync(0xffffffffu, sq, o);
        float inv = 1.0f / fmaxf(sqrt_ap(sq), 1e-12f);
        out[((size_t)bh * 64 + m) * 32 + lane] = k4 * inv;
    }
}

// ---------------------------------------------------------------------------
// K3: rpb[bh][l][m] = exp(-dist(pixel l, center[bh][m]))
// grid (256 pixel-groups, 64 bh); block 256 = 16 pixels x 16 m-quads
// ---------------------------------------------------------------------------
__global__ void __launch_bounds__(256) k_rpb(float* __restrict__ out) {
    int bh = blockIdx.y;
    __shared__ float2 sc[MM];
    if (threadIdx.x < 64)
        sc[threadIdx.x] = ((const float2*)(g_centers + (size_t)bh * 128))[threadIdx.x];
    __syncthreads();

    int pix = threadIdx.x >> 4;     // 0..15
    int mg  = threadIdx.x & 15;     // 0..15 (quad of m)
    int l = blockIdx.x * 16 + pix;
    float fi = (float)(l >> 6), fj = (float)(l & 63);
    float4 r;
#pragma unroll
    for (int q = 0; q < 4; q++) {
        float2 c = sc[mg * 4 + q];
        float dh = fi - c.x, dw = fj - c.y;
        (&r.x)[q] = __expf(-sqrt_ap(dh * dh + dw * dw));
    }
    ((float4*)(out + 262144))[(size_t)bh * 65536 + (size_t)l * 16 + mg] = r;
}

// ---------------------------------------------------------------------------
extern "C" void kernel_launch(void* const* d_in, const int* in_sizes, int n_in,
                              void* d_out, int out_size) {
    const float* xk    = (const float*)d_in[0];
    const float* xv    = (const float*)d_in[1];
    const float* scale = (const float*)d_in[2];
    float* out = (float*)d_out;

    k_rpb0<<<256, 256>>>();
    k_cq0<<<4096, 256>>>(xk);
    dim3 g2(8, 64);
    k_assign<<<g2, 512>>>(xk, scale);
    k_gather<<<4096, 128>>>(xk, xv, out);
    dim3 g3(256, 64);
    k_rpb<<<g3, 256>>>(out);
}

// round 3
// speedup vs baseline: 1.1386x; 1.1356x over previous
#include <cuda_runtime.h>
#include <cstdint>

#define BH    64          // B*h
#define DIM   32          // d
#define LPIX  4096        // H*W
#define MM    64          // number of clusters (L_)
#define QK_SCALE 0.17677669529663687f

// ---- device scratch (no allocations allowed) ----
__device__ __align__(256) float g_cq0[BH * MM * DIM];        // 512 KB
__device__ __align__(256) float g_rpb0[LPIX * MM];           // 1 MB (input-independent)
__device__ __align__(256) unsigned char g_assign[BH * LPIX]; // 256 KB
__device__ __align__(256) float g_centers[BH * MM * 2];      // 32 KB

__device__ __forceinline__ float sqrt_ap(float x) {
    float y; asm("sqrt.approx.f32 %0, %1;" : "=f"(y) : "f"(x)); return y;
}

// ---------------------------------------------------------------------------
// K0: rpb0[l][m] = exp(-dist(pixel l, fixed window center m))  (no input dep)
// ---------------------------------------------------------------------------
__global__ void k_rpb0() {
    int idx = blockIdx.x * 256 + threadIdx.x;   // over LPIX*MM/4 float4s
    int m0 = (idx & 15) * 4;
    int l  = idx >> 4;
    float fi = (float)(l >> 6), fj = (float)(l & 63);
    float4 r;
    float* rp = &r.x;
#pragma unroll
    for (int q = 0; q < 4; q++) {
        int m = m0 + q;
        float ch = (float)((m >> 3) << 3) + 3.5f;
        float cw = (float)((m & 7) << 3) + 3.5f;
        float dh = fi - ch, dw = fj - cw;
        rp[q] = __expf(-sqrt_ap(dh * dh + dw * dw));
    }
    ((float4*)g_rpb0)[idx] = r;
}

// ---------------------------------------------------------------------------
// K1: c_q0[bh][m][:] = l2norm(mean over 8x8 window of x_k)
// ---------------------------------------------------------------------------
__global__ void k_cq0(const float* __restrict__ xk) {
    int blk = blockIdx.x;
    int bh = blk >> 6, m = blk & 63;
    int wr = m >> 3, wc = m & 7;
    int warp = threadIdx.x >> 5, lane = threadIdx.x & 31;

    const float* row = xk + (size_t)bh * LPIX * DIM
                          + ((size_t)(wr * 8 + warp) * 64 + wc * 8) * DIM;
    float acc = 0.f;
#pragma unroll
    for (int k = 0; k < 8; k++) acc += row[k * 32 + lane];

    __shared__ float s[8][32];
    s[warp][lane] = acc;
    __syncthreads();
    if (warp == 0) {
        float v = 0.f;
#pragma unroll
        for (int w = 0; w < 8; w++) v += s[w][lane];
        v *= (1.0f / 64.0f);
        float sq = v * v;
#pragma unroll
        for (int o = 16; o > 0; o >>= 1) sq += __shfl_xor_sync(0xffffffffu, sq, o);
        float inv = 1.0f / fmaxf(sqrt_ap(sq), 1e-12f);
        g_cq0[((size_t)bh * 64 + m) * 32 + lane] = v * inv;
    }
}

// ---------------------------------------------------------------------------
// K2a: per-pixel argmax over 64 clusters of qs*<x_k, c_q0> + rpb0
// ---------------------------------------------------------------------------
__global__ void __launch_bounds__(512) k_assign(const float* __restrict__ xk,
                                                const float* __restrict__ scale) {
    int bh = blockIdx.y;
    int l  = blockIdx.x * 512 + threadIdx.x;

    __shared__ float4 scq[MM * 8];  // 64 clusters x 32 floats
    const float4* gq = (const float4*)(g_cq0 + (size_t)bh * MM * DIM);
    scq[threadIdx.x] = gq[threadIdx.x];
    __syncthreads();

    float qs = QK_SCALE * scale[0];
    float xq[32];
    const float4* xr = (const float4*)(xk + (size_t)bh * LPIX * DIM + (size_t)l * DIM);
#pragma unroll
    for (int k = 0; k < 8; k++) {
        float4 v = xr[k];
        xq[4 * k + 0] = v.x * qs; xq[4 * k + 1] = v.y * qs;
        xq[4 * k + 2] = v.z * qs; xq[4 * k + 3] = v.w * qs;
    }

    const float4* rp = (const float4*)(g_rpb0 + (size_t)l * MM);
    float maxv = -1e30f;
    int argm = 0;
    for (int mq = 0; mq < 16; mq++) {
        float4 rb = rp[mq];
        float a0 = rb.x, a1 = rb.y, a2 = rb.z, a3 = rb.w;
#pragma unroll
        for (int k = 0; k < 8; k++) {
            float4 c0 = scq[(4 * mq + 0) * 8 + k];
            float4 c1 = scq[(4 * mq + 1) * 8 + k];
            float4 c2 = scq[(4 * mq + 2) * 8 + k];
            float4 c3 = scq[(4 * mq + 3) * 8 + k];
            float x0 = xq[4 * k + 0], x1 = xq[4 * k + 1],
                  x2 = xq[4 * k + 2], x3 = xq[4 * k + 3];
            a0 += x0 * c0.x + x1 * c0.y + x2 * c0.z + x3 * c0.w;
            a1 += x0 * c1.x + x1 * c1.y + x2 * c1.z + x3 * c1.w;
            a2 += x0 * c2.x + x1 * c2.y + x2 * c2.z + x3 * c2.w;
            a3 += x0 * c3.x + x1 * c3.y + x2 * c3.z + x3 * c3.w;
        }
        if (a0 > maxv) { maxv = a0; argm = 4 * mq + 0; }
        if (a1 > maxv) { maxv = a1; argm = 4 * mq + 1; }
        if (a2 > maxv) { maxv = a2; argm = 4 * mq + 2; }
        if (a3 > maxv) { maxv = a3; argm = 4 * mq + 3; }
    }
    g_assign[(size_t)bh * LPIX + l] = (unsigned char)argm;
}

// ---------------------------------------------------------------------------
// K2b v2: per (bh, m) gather with COMPACTION + UNROLLED (MLP-8) loads.
// 256 threads = 8 warps. Phase 1: build compact pixel-index list (no atomics).
// Phase 2: warps take contiguous chunks, 4 entries/iter -> 8 concurrent loads.
// ---------------------------------------------------------------------------
__global__ void __launch_bounds__(256) k_gather(const float* __restrict__ xk,
                                                const float* __restrict__ xv,
                                                float* __restrict__ out) {
    int blk = blockIdx.x;
    int bh = blk >> 6, m = blk & 63;
    int warp = threadIdx.x >> 5, lane = threadIdx.x & 31;

    __shared__ unsigned char sa[LPIX];          // 4 KB
    __shared__ unsigned short slist[LPIX];      // 8 KB (worst case all match)
    __shared__ int swcnt[8], soff[8], sn;
    __shared__ float sk[8][32], sv[8][32], ssi[8], ssj[8];

    // load assignments for this bh
    const uint4* ga = (const uint4*)(g_assign + (size_t)bh * LPIX);  // 256 uint4
    ((uint4*)sa)[threadIdx.x] = ga[threadIdx.x];
    __syncthreads();

    unsigned char mmv = (unsigned char)m;
    int base = warp * 512;

    // ---- phase 1a: count matches in this warp's 512-pixel range
    int tw = 0;
    unsigned int matches[16];
#pragma unroll
    for (int it = 0; it < 16; ++it) {
        unsigned int match = __ballot_sync(0xffffffffu,
                                sa[base + it * 32 + lane] == mmv);
        matches[it] = match;
        tw += __popc(match);
    }
    if (lane == 0) swcnt[warp] = tw;
    __syncthreads();

    // ---- phase 1b: exclusive prefix over 8 warp counts
    if (threadIdx.x == 0) {
        int run = 0;
#pragma unroll
        for (int w = 0; w < 8; w++) { soff[w] = run; run += swcnt[w]; }
        sn = run;
    }
    __syncthreads();

    // ---- phase 1c: write indices
    {
        int pos = soff[warp];
        unsigned int ltmask = (1u << lane) - 1u;
#pragma unroll
        for (int it = 0; it < 16; ++it) {
            unsigned int match = matches[it];
            if (match & (1u << lane))
                slist[pos + __popc(match & ltmask)] =
                    (unsigned short)(base + it * 32 + lane);
            pos += __popc(match);
        }
    }
    __syncthreads();

    int n = sn;
    const float* xkb = xk + (size_t)bh * LPIX * DIM;
    const float* xvb = xv + (size_t)bh * LPIX * DIM;

    // ---- phase 2: gather, 4 entries per iteration (8 outstanding 128B loads)
    float accK = 0.f, accV = 0.f, si = 0.f, sj = 0.f;
    int per = (n + 7) >> 3;
    int s0 = warp * per;
    int e1 = min(s0 + per, n);
    int e = s0;
    for (; e + 3 < e1; e += 4) {
        int l0 = slist[e], l1 = slist[e + 1], l2 = slist[e + 2], l3 = slist[e + 3];
        float k0 = __ldg(xkb + l0 * 32 + lane);
        float k1 = __ldg(xkb + l1 * 32 + lane);
        float k2 = __ldg(xkb + l2 * 32 + lane);
        float k3 = __ldg(xkb + l3 * 32 + lane);
        float v0 = __ldg(xvb + l0 * 32 + lane);
        float v1 = __ldg(xvb + l1 * 32 + lane);
        float v2 = __ldg(xvb + l2 * 32 + lane);
        float v3 = __ldg(xvb + l3 * 32 + lane);
        accK += (k0 + k1) + (k2 + k3);
        accV += (v0 + v1) + (v2 + v3);
        si += (float)((l0 >> 6) + (l1 >> 6) + (l2 >> 6) + (l3 >> 6));
        sj += (float)((l0 & 63) + (l1 & 63) + (l2 & 63) + (l3 & 63));
    }
    for (; e < e1; ++e) {
        int l0 = slist[e];
        accK += __ldg(xkb + l0 * 32 + lane);
        accV += __ldg(xvb + l0 * 32 + lane);
        si += (float)(l0 >> 6);
        sj += (float)(l0 & 63);
    }

    sk[warp][lane] = accK;
    sv[warp][lane] = accV;
    if (lane == 0) { ssi[warp] = si; ssj[warp] = sj; }
    __syncthreads();

    if (warp == 0) {
        float k8 = 0.f, v8 = 0.f, tsi = 0.f, tsj = 0.f;
#pragma unroll
        for (int w = 0; w < 8; w++) {
            k8 += sk[w][lane];
            v8 += sv[w][lane];
            tsi += ssi[w];
            tsj += ssj[w];
        }
        float denom = (n > 0) ? (float)n : 1.0f;   // matches s==0 -> 1 guard

        if (lane == 0) {
            g_centers[((size_t)bh * 64 + m) * 2 + 0] = tsi / denom;
            g_centers[((size_t)bh * 64 + m) * 2 + 1] = tsj / denom;
        }
        // c_v
        out[131072 + ((size_t)bh * 64 + m) * 32 + lane] = v8 / denom;
        // c_q = l2norm(sum)
        float sq = k8 * k8;
#pragma unroll
        for (int o = 16; o > 0; o >>= 1) sq += __shfl_xor_sync(0xffffffffu, sq, o);
        float inv = 1.0f / fmaxf(sqrt_ap(sq), 1e-12f);
        out[((size_t)bh * 64 + m) * 32 + lane] = k8 * inv;
    }
}

// ---------------------------------------------------------------------------
// K3: rpb[bh][l][m] = exp(-dist(pixel l, center[bh][m]))
// ---------------------------------------------------------------------------
__global__ void __launch_bounds__(256) k_rpb(float* __restrict__ out) {
    int bh = blockIdx.y;
    __shared__ float2 sc[MM];
    if (threadIdx.x < 64)
        sc[threadIdx.x] = ((const float2*)(g_centers + (size_t)bh * 128))[threadIdx.x];
    __syncthreads();

    int pix = threadIdx.x >> 4;     // 0..15
    int mg  = threadIdx.x & 15;     // 0..15 (quad of m)
    int l = blockIdx.x * 16 + pix;
    float fi = (float)(l >> 6), fj = (float)(l & 63);
    float4 r;
#pragma unroll
    for (int q = 0; q < 4; q++) {
        float2 c = sc[mg * 4 + q];
        float dh = fi - c.x, dw = fj - c.y;
        (&r.x)[q] = __expf(-sqrt_ap(dh * dh + dw * dw));
    }
    ((float4*)(out + 262144))[(size_t)bh * 65536 + (size_t)l * 16 + mg] = r;
}

// ---------------------------------------------------------------------------
extern "C" void kernel_launch(void* const* d_in, const int* in_sizes, int n_in,
                              void* d_out, int out_size) {
    const float* xk    = (const float*)d_in[0];
    const float* xv    = (const float*)d_in[1];
    const float* scale = (const float*)d_in[2];
    float* out = (float*)d_out;

    k_rpb0<<<256, 256>>>();
    k_cq0<<<4096, 256>>>(xk);
    dim3 g2(8, 64);
    k_assign<<<g2, 512>>>(xk, scale);
    k_gather<<<4096, 256>>>(xk, xv, out);
    dim3 g3(256, 64);
    k_rpb<<<g3, 256>>>(out);
}